// round 4
// baseline (speedup 1.0000x reference)
#include <cuda_runtime.h>
#include <cuda_bf16.h>
#include <cstdint>

#define N 4096
#define D 1024
#define EPSV 1e-8f
#define MARGIN 0.1f

#define BM 256
#define BN 128
#define BK 64          // 64 bf16 = 128 B per smem row (SW128 atom)
#define NKC (D / BK)   // 16 k-chunks
#define NCTAS ((N / BM) * (N / BN))   // 512

// ---------------- device globals (scratch) -----------------------------------
__device__ float  g_nw[N];
__device__ float  g_no[N];
__device__ float  g_d[N];
__device__ double g_acc = 0.0;
__device__ unsigned int g_ticket = 0;
__device__ __nv_bfloat16 g_Wb[(size_t)N * D];
__device__ __nv_bfloat16 g_Ob[(size_t)N * D];

// ---------------- helpers ----------------------------------------------------
__device__ __forceinline__ uint32_t smem_u32(const void* p) {
    uint32_t a;
    asm("{ .reg .u64 t; cvta.to.shared.u64 t, %1; cvt.u32.u64 %0, t; }" : "=r"(a) : "l"(p));
    return a;
}
__device__ __forceinline__ float warp_sum(float v) {
    #pragma unroll
    for (int off = 16; off > 0; off >>= 1) v += __shfl_down_sync(0xFFFFFFFFu, v, off);
    return v;
}
__device__ __forceinline__ uint32_t swz128(uint32_t off) { return off ^ ((off >> 3) & 0x70); }

__device__ __forceinline__ void cp_async16(uint32_t saddr, const void* gaddr) {
    asm volatile("cp.async.cg.shared.global [%0], [%1], 16;" :: "r"(saddr), "l"(gaddr));
}
#define CP_COMMIT() asm volatile("cp.async.commit_group;" ::: "memory")
#define CP_WAIT1()  asm volatile("cp.async.wait_group 1;" ::: "memory")
#define CP_WAIT0()  asm volatile("cp.async.wait_group 0;" ::: "memory")

__device__ __forceinline__ void ldsm_x4(uint32_t* r, uint32_t addr) {
    asm volatile("ldmatrix.sync.aligned.m8n8.x4.shared.b16 {%0,%1,%2,%3}, [%4];"
                 : "=r"(r[0]), "=r"(r[1]), "=r"(r[2]), "=r"(r[3]) : "r"(addr));
}
__device__ __forceinline__ void mma_bf16(float* c, const uint32_t* a, const uint32_t* b) {
    asm volatile(
        "mma.sync.aligned.m16n8k16.row.col.f32.bf16.bf16.f32 "
        "{%0,%1,%2,%3}, {%4,%5,%6,%7}, {%8,%9}, {%0,%1,%2,%3};"
        : "+f"(c[0]), "+f"(c[1]), "+f"(c[2]), "+f"(c[3])
        : "r"(a[0]), "r"(a[1]), "r"(a[2]), "r"(a[3]), "r"(b[0]), "r"(b[1]));
}

// ---------------- kernel 1: row stats + fp32->bf16 (2 rows / block) ----------
__global__ void row_stats_kernel(const float* __restrict__ W, const float* __restrict__ O) {
    const int t   = threadIdx.x;
    const int half = t >> 7;           // 0: row0, 1: row1
    const int tt   = t & 127;
    const int row  = blockIdx.x * 2 + half;

    const float4* W4 = reinterpret_cast<const float4*>(W + (size_t)row * D);
    const float4* O4 = reinterpret_cast<const float4*>(O + (size_t)row * D);
    const float4 a0 = W4[tt], a1 = W4[tt + 128];
    const float4 b0 = O4[tt], b1 = O4[tt + 128];

    // bf16 conversion + store (4x uint2)
    uint2* Wb2 = reinterpret_cast<uint2*>(g_Wb + (size_t)row * D);
    uint2* Ob2 = reinterpret_cast<uint2*>(g_Ob + (size_t)row * D);
    {
        __nv_bfloat162 x0 = __floats2bfloat162_rn(a0.x, a0.y);
        __nv_bfloat162 x1 = __floats2bfloat162_rn(a0.z, a0.w);
        Wb2[tt] = make_uint2(*(uint32_t*)&x0, *(uint32_t*)&x1);
        __nv_bfloat162 y0 = __floats2bfloat162_rn(a1.x, a1.y);
        __nv_bfloat162 y1 = __floats2bfloat162_rn(a1.z, a1.w);
        Wb2[tt + 128] = make_uint2(*(uint32_t*)&y0, *(uint32_t*)&y1);
        __nv_bfloat162 z0 = __floats2bfloat162_rn(b0.x, b0.y);
        __nv_bfloat162 z1 = __floats2bfloat162_rn(b0.z, b0.w);
        Ob2[tt] = make_uint2(*(uint32_t*)&z0, *(uint32_t*)&z1);
        __nv_bfloat162 w0 = __floats2bfloat162_rn(b1.x, b1.y);
        __nv_bfloat162 w1 = __floats2bfloat162_rn(b1.z, b1.w);
        Ob2[tt + 128] = make_uint2(*(uint32_t*)&w0, *(uint32_t*)&w1);
    }

    float ww = a0.x*a0.x + a0.y*a0.y + a0.z*a0.z + a0.w*a0.w
             + a1.x*a1.x + a1.y*a1.y + a1.z*a1.z + a1.w*a1.w;
    float oo = b0.x*b0.x + b0.y*b0.y + b0.z*b0.z + b0.w*b0.w
             + b1.x*b1.x + b1.y*b1.y + b1.z*b1.z + b1.w*b1.w;
    float wo = a0.x*b0.x + a0.y*b0.y + a0.z*b0.z + a0.w*b0.w
             + a1.x*b1.x + a1.y*b1.y + a1.z*b1.z + a1.w*b1.w;

    ww = warp_sum(ww); oo = warp_sum(oo); wo = warp_sum(wo);

    __shared__ float sw[8], so[8], sd[8];
    const int lane = t & 31, wid = t >> 5;
    if (lane == 0) { sw[wid] = ww; so[wid] = oo; sd[wid] = wo; }
    __syncthreads();
    if ((t & 127) == 0) {   // t==0 (row0) and t==128 (row1)
        const int base = half * 4;
        float vw = sw[base] + sw[base+1] + sw[base+2] + sw[base+3];
        float vo = so[base] + so[base+1] + so[base+2] + so[base+3];
        float vd = sd[base] + sd[base+1] + sd[base+2] + sd[base+3];
        float nw = sqrtf(vw), no = sqrtf(vo);
        g_nw[row] = nw; g_no[row] = no;
        g_d[row]  = vd / fmaxf(nw * no, EPSV);
    }
}

// ---------------- kernel 2: mma.sync bf16 GEMM + fused loss + finalize -------
// dynamic smem: A x3 stages (32 KB each), B x3 stages (16 KB each), stats
#define A_BYTES  (BM * 128)                  // 32768
#define B_BYTES  (BN * 128)                  // 16384
#define SM_A(s)  ((s) * A_BYTES)             // 0, 32K, 64K
#define SM_B(s)  (3 * A_BYTES + (s) * B_BYTES)
#define SM_NW    (3 * A_BYTES + 3 * B_BYTES)        // 147456
#define SM_D     (SM_NW + BM * 4)
#define SM_NO    (SM_D  + BM * 4)
#define SM_TOTAL (SM_NO + BN * 4)                    // 150016

__global__ __launch_bounds__(512, 1)
void gemm_loss_mma(float* __restrict__ out) {
    extern __shared__ char smem[];
    const uint32_t sbase = smem_u32(smem);
    const int tid  = threadIdx.x;
    const int wid  = tid >> 5;
    const int lane = tid & 31;
    const int bi = blockIdx.y;
    const int bj = blockIdx.x;
    const int warp_m = wid >> 2;       // 0..3  (64 rows each)
    const int warp_n = wid & 3;        // 0..3  (32 cols each)

    // stage per-row/col stats
    if (tid < 256) {
        reinterpret_cast<float*>(smem + SM_NW)[tid] = g_nw[bi * BM + tid];
        reinterpret_cast<float*>(smem + SM_D )[tid] = g_d [bi * BM + tid];
        if (tid < 128)
            reinterpret_cast<float*>(smem + SM_NO)[tid] = g_no[bj * BN + tid];
    }

    const __nv_bfloat16* __restrict__ Wt = g_Wb + (size_t)(bi * BM) * D;
    const __nv_bfloat16* __restrict__ Ot = g_Ob + (size_t)(bj * BN) * D;

    // per-stage loads: A 2048 16B-chunks (4/thread), B 1024 (2/thread)
    const int lrow = tid >> 3;     // A rows: lrow + 64*i ; B rows: lrow + 64*i (i<2)
    const int lcol = tid & 7;

    float acc[4][4][4];
    #pragma unroll
    for (int f = 0; f < 4; ++f)
        #pragma unroll
        for (int g = 0; g < 4; ++g)
            #pragma unroll
            for (int r = 0; r < 4; ++r) acc[f][g][r] = 0.f;

    const int a_row = warp_m * 64 + ((lane >> 3) & 1) * 8 + (lane & 7); // + f*16
    const int a_cb  = (lane >> 4) * 16;                                  // + ks*32
    const int b_row = warp_n * 32 + ((lane >> 4) & 1) * 8 + (lane & 7); // + nf2*16
    const int b_cb  = ((lane >> 3) & 1) * 16;                            // + ks*32

    // prologue: stages for kc=0,1
    #pragma unroll
    for (int kc = 0; kc < 2; ++kc) {
        const int kt = kc * BK;
        const uint32_t sa = sbase + SM_A(kc);
        const uint32_t sb = sbase + SM_B(kc);
        #pragma unroll
        for (int i = 0; i < 4; ++i) {
            int row = lrow + i * 64;
            cp_async16(sa + swz128(row * 128 + lcol * 16),
                       Wt + (size_t)row * D + kt + lcol * 8);
        }
        #pragma unroll
        for (int i = 0; i < 2; ++i) {
            int row = lrow + i * 64;
            cp_async16(sb + swz128(row * 128 + lcol * 16),
                       Ot + (size_t)row * D + kt + lcol * 8);
        }
        CP_COMMIT();
    }

    int stage = 0;
    #pragma unroll 1
    for (int kc = 0; kc < NKC; ++kc) {
        if (kc + 2 < NKC) CP_WAIT1(); else if (kc + 1 < NKC) CP_WAIT1(); else CP_WAIT0();
        __syncthreads();

        if (kc + 2 < NKC) {
            // stage (kc+2)%3 == buffer of chunk kc-1, consumed by all warps (barrier above)
            const int kt = (kc + 2) * BK;
            const int ns = (stage + 2) % 3;
            const uint32_t sa = sbase + SM_A(ns);
            const uint32_t sb = sbase + SM_B(ns);
            #pragma unroll
            for (int i = 0; i < 4; ++i) {
                int row = lrow + i * 64;
                cp_async16(sa + swz128(row * 128 + lcol * 16),
                           Wt + (size_t)row * D + kt + lcol * 8);
            }
            #pragma unroll
            for (int i = 0; i < 2; ++i) {
                int row = lrow + i * 64;
                cp_async16(sb + swz128(row * 128 + lcol * 16),
                           Ot + (size_t)row * D + kt + lcol * 8);
            }
            CP_COMMIT();
        }

        const uint32_t abuf = sbase + SM_A(stage);
        const uint32_t bbuf = sbase + SM_B(stage);

        #pragma unroll
        for (int ks = 0; ks < 4; ++ks) {
            uint32_t areg[4][4];
            uint32_t breg[2][4];
            #pragma unroll
            for (int f = 0; f < 4; ++f)
                ldsm_x4(areg[f], abuf + swz128((a_row + f * 16) * 128 + a_cb + ks * 32));
            #pragma unroll
            for (int nf2 = 0; nf2 < 2; ++nf2)
                ldsm_x4(breg[nf2], bbuf + swz128((b_row + nf2 * 16) * 128 + b_cb + ks * 32));
            #pragma unroll
            for (int f = 0; f < 4; ++f)
                #pragma unroll
                for (int g = 0; g < 4; ++g)
                    mma_bf16(acc[f][g], areg[f], &breg[g >> 1][(g & 1) * 2]);
        }
        stage = (stage + 1) % 3;
        // no trailing barrier: next iteration's barrier protects buffer reuse
    }

    // ---- fused epilogue ------------------------------------------------------
    const float* snw = reinterpret_cast<const float*>(smem + SM_NW);
    const float* sd  = reinterpret_cast<const float*>(smem + SM_D);
    const float* sno = reinterpret_cast<const float*>(smem + SM_NO);

    const int qrow = lane >> 2;
    const int qcol = (lane & 3) * 2;

    float lsum = 0.f;
    #pragma unroll
    for (int f = 0; f < 4; ++f) {
        const int r0 = warp_m * 64 + f * 16 + qrow;
        #pragma unroll
        for (int half = 0; half < 2; ++half) {
            const int rl = r0 + half * 8;
            const int rg = bi * BM + rl;
            const float nw_r = snw[rl];
            const float d_r  = sd[rl];
            #pragma unroll
            for (int g = 0; g < 4; ++g) {
                #pragma unroll
                for (int e = 0; e < 2; ++e) {
                    const int cl = warp_n * 32 + g * 8 + qcol + e;
                    const int jg = bj * BN + cl;
                    const float S = acc[f][g][half * 2 + e] *
                                    __fdividef(1.0f, fmaxf(nw_r * sno[cl], EPSV));
                    lsum += (rg == jg) ? (1.0f - S) : fmaxf(MARGIN - S + d_r, 0.0f);
                }
            }
        }
    }

    lsum = warp_sum(lsum);
    __shared__ float red[16];
    if (lane == 0) red[wid] = lsum;
    __syncthreads();
    if (wid == 0) {
        float v = (lane < 16) ? red[lane] : 0.f;
        v = warp_sum(v);
        if (lane == 0) {
            atomicAdd(&g_acc, (double)v);
            __threadfence();
            unsigned int t = atomicAdd(&g_ticket, 1u);
            if (t == NCTAS - 1) {
                // all CTAs' g_acc contributions visible (fence-before-ticket on each)
                double total;
                asm volatile("ld.global.acquire.gpu.f64 %0, [%1];" : "=d"(total) : "l"(&g_acc));
                out[0] = (float)(total / ((double)N * (double)N));
                g_acc = 0.0;          // reset for next graph replay
                g_ticket = 0u;
                __threadfence();
            }
        }
    }
}

extern "C" void kernel_launch(void* const* d_in, const int* in_sizes, int n_in,
                              void* d_out, int out_size) {
    const float* W = (const float*)d_in[0];
    const float* O = (const float*)d_in[1];
    float* out = (float*)d_out;

    cudaFuncSetAttribute(gemm_loss_mma, cudaFuncAttributeMaxDynamicSharedMemorySize, SM_TOTAL);

    row_stats_kernel<<<N / 2, 256>>>(W, O);

    dim3 grid(N / BN, N / BM);   // (32, 16)
    gemm_loss_mma<<<grid, 512, SM_TOTAL>>>(out);
}

// round 5
// speedup vs baseline: 1.1827x; 1.1827x over previous
#include <cuda_runtime.h>
#include <cuda_bf16.h>
#include <cstdint>

#define N 4096
#define D 1024
#define EPSV 1e-8f
#define MARGIN 0.1f

#define BM 128
#define BN 128
#define BK 64          // 64 bf16 = 128 B per smem row (SW128 atom)
#define NKC (D / BK)   // 16 k-chunks
#define NCTAS ((N / BM) * (N / BN))   // 1024

// ---------------- device globals (scratch) -----------------------------------
__device__ float  g_nw[N];
__device__ float  g_no[N];
__device__ float  g_d[N];
__device__ double g_acc = 0.0;
__device__ unsigned int g_ticket = 0;
__device__ __nv_bfloat16 g_Wb[(size_t)N * D];
__device__ __nv_bfloat16 g_Ob[(size_t)N * D];

// ---------------- helpers ----------------------------------------------------
__device__ __forceinline__ uint32_t smem_u32(const void* p) {
    uint32_t a;
    asm("{ .reg .u64 t; cvta.to.shared.u64 t, %1; cvt.u32.u64 %0, t; }" : "=r"(a) : "l"(p));
    return a;
}
__device__ __forceinline__ float warp_sum(float v) {
    #pragma unroll
    for (int off = 16; off > 0; off >>= 1) v += __shfl_down_sync(0xFFFFFFFFu, v, off);
    return v;
}
__device__ __forceinline__ uint32_t swz128(uint32_t off) { return off ^ ((off >> 3) & 0x70); }

__device__ __forceinline__ void cp_async16(uint32_t saddr, const void* gaddr) {
    asm volatile("cp.async.cg.shared.global [%0], [%1], 16;" :: "r"(saddr), "l"(gaddr));
}
#define CP_COMMIT() asm volatile("cp.async.commit_group;" ::: "memory")
#define CP_WAIT1()  asm volatile("cp.async.wait_group 1;" ::: "memory")
#define CP_WAIT0()  asm volatile("cp.async.wait_group 0;" ::: "memory")

__device__ __forceinline__ void ldsm_x4(uint32_t* r, uint32_t addr) {
    asm volatile("ldmatrix.sync.aligned.m8n8.x4.shared.b16 {%0,%1,%2,%3}, [%4];"
                 : "=r"(r[0]), "=r"(r[1]), "=r"(r[2]), "=r"(r[3]) : "r"(addr));
}
__device__ __forceinline__ void mma_bf16(float* c, const uint32_t* a, const uint32_t* b) {
    asm volatile(
        "mma.sync.aligned.m16n8k16.row.col.f32.bf16.bf16.f32 "
        "{%0,%1,%2,%3}, {%4,%5,%6,%7}, {%8,%9}, {%0,%1,%2,%3};"
        : "+f"(c[0]), "+f"(c[1]), "+f"(c[2]), "+f"(c[3])
        : "r"(a[0]), "r"(a[1]), "r"(a[2]), "r"(a[3]), "r"(b[0]), "r"(b[1]));
}

// ---------------- kernel 1: row stats + fp32->bf16 (2 rows / block) ----------
__global__ void row_stats_kernel(const float* __restrict__ W, const float* __restrict__ O) {
    const int t    = threadIdx.x;
    const int half = t >> 7;
    const int tt   = t & 127;
    const int row  = blockIdx.x * 2 + half;

    const float4* W4 = reinterpret_cast<const float4*>(W + (size_t)row * D);
    const float4* O4 = reinterpret_cast<const float4*>(O + (size_t)row * D);
    const float4 a0 = W4[tt], a1 = W4[tt + 128];
    const float4 b0 = O4[tt], b1 = O4[tt + 128];

    uint2* Wb2 = reinterpret_cast<uint2*>(g_Wb + (size_t)row * D);
    uint2* Ob2 = reinterpret_cast<uint2*>(g_Ob + (size_t)row * D);
    {
        __nv_bfloat162 x0 = __floats2bfloat162_rn(a0.x, a0.y);
        __nv_bfloat162 x1 = __floats2bfloat162_rn(a0.z, a0.w);
        Wb2[tt] = make_uint2(*(uint32_t*)&x0, *(uint32_t*)&x1);
        __nv_bfloat162 y0 = __floats2bfloat162_rn(a1.x, a1.y);
        __nv_bfloat162 y1 = __floats2bfloat162_rn(a1.z, a1.w);
        Wb2[tt + 128] = make_uint2(*(uint32_t*)&y0, *(uint32_t*)&y1);
        __nv_bfloat162 z0 = __floats2bfloat162_rn(b0.x, b0.y);
        __nv_bfloat162 z1 = __floats2bfloat162_rn(b0.z, b0.w);
        Ob2[tt] = make_uint2(*(uint32_t*)&z0, *(uint32_t*)&z1);
        __nv_bfloat162 w0 = __floats2bfloat162_rn(b1.x, b1.y);
        __nv_bfloat162 w1 = __floats2bfloat162_rn(b1.z, b1.w);
        Ob2[tt + 128] = make_uint2(*(uint32_t*)&w0, *(uint32_t*)&w1);
    }

    float ww = a0.x*a0.x + a0.y*a0.y + a0.z*a0.z + a0.w*a0.w
             + a1.x*a1.x + a1.y*a1.y + a1.z*a1.z + a1.w*a1.w;
    float oo = b0.x*b0.x + b0.y*b0.y + b0.z*b0.z + b0.w*b0.w
             + b1.x*b1.x + b1.y*b1.y + b1.z*b1.z + b1.w*b1.w;
    float wo = a0.x*b0.x + a0.y*b0.y + a0.z*b0.z + a0.w*b0.w
             + a1.x*b1.x + a1.y*b1.y + a1.z*b1.z + a1.w*b1.w;

    ww = warp_sum(ww); oo = warp_sum(oo); wo = warp_sum(wo);

    __shared__ float sw[8], so[8], sd[8];
    const int lane = t & 31, wid = t >> 5;
    if (lane == 0) { sw[wid] = ww; so[wid] = oo; sd[wid] = wo; }
    __syncthreads();
    if ((t & 127) == 0) {
        const int base = half * 4;
        float vw = sw[base] + sw[base+1] + sw[base+2] + sw[base+3];
        float vo = so[base] + so[base+1] + so[base+2] + so[base+3];
        float vd = sd[base] + sd[base+1] + sd[base+2] + sd[base+3];
        float nw = sqrtf(vw), no = sqrtf(vo);
        g_nw[row] = nw; g_no[row] = no;
        g_d[row]  = vd / fmaxf(nw * no, EPSV);
    }
}

// ---------------- kernel 2: mma.sync bf16 GEMM, 3-stage pipeline -------------
// per-CTA smem: 3x(A 16KB) + 3x(B 16KB) + stats = 99840 B -> 2 CTAs/SM
#define A_BYTES  (BM * 128)
#define B_BYTES  (BN * 128)
#define SM_A(s)  ((s) * A_BYTES)
#define SM_B(s)  (3 * A_BYTES + (s) * B_BYTES)
#define SM_NW    (3 * A_BYTES + 3 * B_BYTES)
#define SM_D     (SM_NW + BM * 4)
#define SM_NO    (SM_D  + BM * 4)
#define SM_TOTAL (SM_NO + BN * 4)

__global__ __launch_bounds__(256, 2)
void gemm_loss_mma(float* __restrict__ out) {
    extern __shared__ char smem[];
    const uint32_t sbase = smem_u32(smem);
    const int tid  = threadIdx.x;
    const int wid  = tid >> 5;
    const int lane = tid & 31;
    const int bi = blockIdx.y;
    const int bj = blockIdx.x;
    const int warp_m = wid >> 2;       // 0..1 (64 rows each)
    const int warp_n = wid & 3;        // 0..3 (32 cols each)

    if (tid < 128) {
        reinterpret_cast<float*>(smem + SM_NW)[tid] = g_nw[bi * BM + tid];
        reinterpret_cast<float*>(smem + SM_D )[tid] = g_d [bi * BM + tid];
        reinterpret_cast<float*>(smem + SM_NO)[tid] = g_no[bj * BN + tid];
    }

    const __nv_bfloat16* __restrict__ Wt = g_Wb + (size_t)(bi * BM) * D;
    const __nv_bfloat16* __restrict__ Ot = g_Ob + (size_t)(bj * BN) * D;

    const int lrow = tid >> 3;     // 0..31 (+32*i)
    const int lcol = tid & 7;

    float acc[4][4][4];
    #pragma unroll
    for (int f = 0; f < 4; ++f)
        #pragma unroll
        for (int g = 0; g < 4; ++g)
            #pragma unroll
            for (int r = 0; r < 4; ++r) acc[f][g][r] = 0.f;

    const int a_row = warp_m * 64 + ((lane >> 3) & 1) * 8 + (lane & 7);
    const int a_cb  = (lane >> 4) * 16;
    const int b_row = warp_n * 32 + ((lane >> 4) & 1) * 8 + (lane & 7);
    const int b_cb  = ((lane >> 3) & 1) * 16;

    // prologue: stages 0,1 for kc=0,1
    #pragma unroll
    for (int kc = 0; kc < 2; ++kc) {
        const int kt = kc * BK;
        const uint32_t sa = sbase + SM_A(kc);
        const uint32_t sb = sbase + SM_B(kc);
        #pragma unroll
        for (int i = 0; i < 4; ++i) {
            int row = lrow + i * 32;
            cp_async16(sa + swz128(row * 128 + lcol * 16),
                       Wt + (size_t)row * D + kt + lcol * 8);
            cp_async16(sb + swz128(row * 128 + lcol * 16),
                       Ot + (size_t)row * D + kt + lcol * 8);
        }
        CP_COMMIT();
    }

    int stage = 0;
    #pragma unroll 1
    for (int kc = 0; kc < NKC; ++kc) {
        if (kc + 1 < NKC) CP_WAIT1(); else CP_WAIT0();
        __syncthreads();

        if (kc + 2 < NKC) {
            const int kt = (kc + 2) * BK;
            const int ns = (stage + 2) % 3;
            const uint32_t sa = sbase + SM_A(ns);
            const uint32_t sb = sbase + SM_B(ns);
            #pragma unroll
            for (int i = 0; i < 4; ++i) {
                int row = lrow + i * 32;
                cp_async16(sa + swz128(row * 128 + lcol * 16),
                           Wt + (size_t)row * D + kt + lcol * 8);
                cp_async16(sb + swz128(row * 128 + lcol * 16),
                           Ot + (size_t)row * D + kt + lcol * 8);
            }
            CP_COMMIT();
        }

        const uint32_t abuf = sbase + SM_A(stage);
        const uint32_t bbuf = sbase + SM_B(stage);

        #pragma unroll
        for (int ks = 0; ks < 4; ++ks) {
            uint32_t areg[4][4];
            uint32_t breg[2][4];
            #pragma unroll
            for (int f = 0; f < 4; ++f)
                ldsm_x4(areg[f], abuf + swz128((a_row + f * 16) * 128 + a_cb + ks * 32));
            #pragma unroll
            for (int nf2 = 0; nf2 < 2; ++nf2)
                ldsm_x4(breg[nf2], bbuf + swz128((b_row + nf2 * 16) * 128 + b_cb + ks * 32));
            #pragma unroll
            for (int f = 0; f < 4; ++f)
                #pragma unroll
                for (int g = 0; g < 4; ++g)
                    mma_bf16(acc[f][g], areg[f], &breg[g >> 1][(g & 1) * 2]);
        }
        stage = (stage + 1) % 3;
    }

    // ---- fused epilogue ------------------------------------------------------
    const float* snw = reinterpret_cast<const float*>(smem + SM_NW);
    const float* sd  = reinterpret_cast<const float*>(smem + SM_D);
    const float* sno = reinterpret_cast<const float*>(smem + SM_NO);

    const int qrow = lane >> 2;
    const int qcol = (lane & 3) * 2;

    float lsum = 0.f;
    #pragma unroll
    for (int f = 0; f < 4; ++f) {
        const int r0 = warp_m * 64 + f * 16 + qrow;
        #pragma unroll
        for (int half = 0; half < 2; ++half) {
            const int rl = r0 + half * 8;
            const int rg = bi * BM + rl;
            const float nw_r = snw[rl];
            const float d_r  = sd[rl];
            #pragma unroll
            for (int g = 0; g < 4; ++g) {
                #pragma unroll
                for (int e = 0; e < 2; ++e) {
                    const int cl = warp_n * 32 + g * 8 + qcol + e;
                    const int jg = bj * BN + cl;
                    const float S = acc[f][g][half * 2 + e] *
                                    __fdividef(1.0f, fmaxf(nw_r * sno[cl], EPSV));
                    lsum += (rg == jg) ? (1.0f - S) : fmaxf(MARGIN - S + d_r, 0.0f);
                }
            }
        }
    }

    lsum = warp_sum(lsum);
    __shared__ float red[8];
    if (lane == 0) red[wid] = lsum;
    __syncthreads();
    if (wid == 0) {
        float v = (lane < 8) ? red[lane] : 0.f;
        v = warp_sum(v);
        if (lane == 0) {
            atomicAdd(&g_acc, (double)v);
            __threadfence();
            unsigned int t = atomicAdd(&g_ticket, 1u);
            if (t == NCTAS - 1) {
                double total;
                asm volatile("ld.global.acquire.gpu.f64 %0, [%1];" : "=d"(total) : "l"(&g_acc));
                out[0] = (float)(total / ((double)N * (double)N));
                g_acc = 0.0;
                g_ticket = 0u;
                __threadfence();
            }
        }
    }
}

extern "C" void kernel_launch(void* const* d_in, const int* in_sizes, int n_in,
                              void* d_out, int out_size) {
    const float* W = (const float*)d_in[0];
    const float* O = (const float*)d_in[1];
    float* out = (float*)d_out;

    cudaFuncSetAttribute(gemm_loss_mma, cudaFuncAttributeMaxDynamicSharedMemorySize, SM_TOTAL);

    row_stats_kernel<<<N / 2, 256>>>(W, O);

    dim3 grid(N / BN, N / BM);   // (32, 32)
    gemm_loss_mma<<<grid, 256, SM_TOTAL>>>(out);
}